// round 14
// baseline (speedup 1.0000x reference)
#include <cuda_runtime.h>
#include <math.h>

// Shapes (fixed): x = (4,8,8192,128) fp32
#define NBH     32
#define SLEN    8192
#define DIMC    128
#define NREG    96
#define NOUTC   32
#define TPB     128
#define RPB     256   // rows per block (2 per thread)
#define NCHUNK  64
#define CHUNK_S 128   // SLEN / NCHUNK

#define PAIR_OFF   4624                       // floats; 18496 B == 64 mod 128 -> disjoint banks
#define PAIR_OFF_O 528                        // floats; 2112 B == 64 mod 128

#define SCR_STRIDE 129                        // conflict-free scattered access
#define SCR_FLOATS (RPB * SCR_STRIDE)         // 33024
#define OFF_M      SCR_FLOATS                 // pair regions (2 x 48 x 96) + pad
#define OFF_RO     (OFF_M + 9248)             // shRo: 32*32
#define OFF_SO     (OFF_RO + 1024)            // shSo: 32*32 + pair pad
#define OFF_ORD    (OFF_SO + 1040)            // 128 ints
#define OFF_CSR    (OFF_ORD + DIMC)           // colsum(rotR): 96
#define SMEM_FLOATS (OFF_CSR + NREG)
#define SMEM_BYTES  (SMEM_FLOATS * 4)         // ~178 KB -> 1 block/SM

typedef unsigned long long ull;

// static device scratch (no runtime allocation)
__device__ float g_partial[NBH * NCHUNK * DIMC];
__device__ int   g_order[NBH * DIMC];
__device__ float g_colR[NREG];

// ---------------------------------------------------------------------------
// packed f32x2 helpers (FFMA2 path on sm_103a)
// ---------------------------------------------------------------------------
__device__ __forceinline__ ull pack2(float lo, float hi)
{
    ull r;
    asm("mov.b64 %0, {%1, %2};" : "=l"(r) : "f"(lo), "f"(hi));
    return r;
}
__device__ __forceinline__ void unpack2(ull p, float& lo, float& hi)
{
    asm("mov.b64 {%0, %1}, %2;" : "=f"(lo), "=f"(hi) : "l"(p));
}
__device__ __forceinline__ ull fma2(ull a, ull b, ull c)
{
    ull d;
    asm("fma.rn.f32x2 %0, %1, %2, %3;" : "=l"(d) : "l"(a), "l"(b), "l"(c));
    return d;
}
__device__ __forceinline__ ull mul2(ull a, ull b)
{
    ull d;
    asm("mul.rn.f32x2 %0, %1, %2;" : "=l"(d) : "l"(a), "l"(b));
    return d;
}

// ---------------------------------------------------------------------------
// Stage A: partial channel sum-of-squares (coalesced)
// ---------------------------------------------------------------------------
__global__ void __launch_bounds__(DIMC) k_chnorm(const float* __restrict__ x)
{
    int bh = blockIdx.y, ck = blockIdx.x, c = threadIdx.x;
    const float* p = x + ((size_t)bh * SLEN + (size_t)ck * CHUNK_S) * DIMC + c;
    float acc = 0.f;
#pragma unroll 8
    for (int s = 0; s < CHUNK_S; ++s) {
        float t = p[(size_t)s * DIMC];
        acc = fmaf(t, t, acc);
    }
    g_partial[(bh * NCHUNK + ck) * DIMC + c] = acc;
}

// ---------------------------------------------------------------------------
// Stage B: reduce + top-32 membership + stable order (non-outliers first)
// ---------------------------------------------------------------------------
__global__ void __launch_bounds__(DIMC) k_order()
{
    __shared__ float nsq[DIMC];
    __shared__ int   flag[DIMC];
    int bh = blockIdx.x, c = threadIdx.x;
    float a = 0.f;
    for (int k = 0; k < NCHUNK; ++k) a += g_partial[(bh * NCHUNK + k) * DIMC + c];
    nsq[c] = a;
    __syncthreads();
    int rank = 0;
    for (int d = 0; d < DIMC; ++d) {
        float nd = nsq[d];
        rank += (nd > a) || (nd == a && d < c);   // top_k ties: lower index wins
    }
    int isout = (rank < NOUTC) ? 1 : 0;
    flag[c] = isout;
    __syncthreads();
    int pos = 0;
    for (int d = 0; d < c; ++d) pos += (flag[d] == isout);
    g_order[bh * DIMC + (isout ? (NREG + pos) : pos)] = c;
}

// ---------------------------------------------------------------------------
// Stage B2: column sums of rotR (input constant)
// ---------------------------------------------------------------------------
__global__ void __launch_bounds__(DIMC) k_colsum(const float* __restrict__ rotR)
{
    int j = threadIdx.x;
    if (j < NREG) {
        float a = 0.f;
        for (int i = 0; i < NREG; ++i) a += rotR[i * NREG + j];
        g_colR[j] = a;
    }
}

// ---------------------------------------------------------------------------
// per-row reconstruction helpers (pair FFMA2, bank-disjoint, jg=16 groups)
// ---------------------------------------------------------------------------
__device__ __forceinline__ float rec_pass2(
    ull* vp, const float* shM, const float* shCsR,
    unsigned w0, unsigned w1, unsigned w2,
    ull cmidp, ull chalfp, ull nrmp)
{
    const ull onep = pack2(1.f, 1.f), negonep = pack2(-1.f, -1.f);
    ull rsq2 = 0ull;
#pragma unroll
    for (int jg = 0; jg < NREG; jg += 16) {
        ull A[8];
#pragma unroll
        for (int k = 0; k < 8; ++k) A[k] = 0ull;
#pragma unroll
        for (int wi = 0; wi < 3; ++wi) {
            unsigned w = (wi == 0) ? w0 : ((wi == 1) ? w1 : w2);
            const float* bp = shM + (wi * 16) * NREG + jg;
#pragma unroll 2
            for (int p = 0; p < 16; ++p) {
                unsigned be = (w >> (2 * p)) & 1u;
                unsigned bx = ((w >> (2 * p)) ^ (w >> (2 * p + 1))) & 1u;
                const ulonglong2* src = (const ulonglong2*)(bx ? (bp + PAIR_OFF) : bp);
                ull s2 = be ? onep : negonep;
#pragma unroll
                for (int t = 0; t < 4; ++t) {
                    ulonglong2 m = src[t];
                    A[2 * t]     = fma2(s2, m.x, A[2 * t]);
                    A[2 * t + 1] = fma2(s2, m.y, A[2 * t + 1]);
                }
                bp += NREG;
            }
        }
#pragma unroll
        for (int k = 0; k < 8; ++k) {
            ull cs2 = *(const ull*)(shCsR + jg + 2 * k);
            ull t = mul2(cmidp, cs2);
            t = fma2(chalfp, A[k], t);
            ull xm2 = mul2(t, nrmp);
            ull r2 = fma2(xm2, negonep, vp[jg / 2 + k]);
            vp[jg / 2 + k] = r2;
            rsq2 = fma2(r2, r2, rsq2);
        }
    }
    float rl, rh;
    unpack2(rsq2, rl, rh);
    return fmaxf(sqrtf(rl + rh), 1e-10f);
}

__device__ __forceinline__ void rec_pass4(
    const ull* vp, const float* shM, const int* shOrd, float* myscr,
    unsigned g0, unsigned g1, unsigned g2, float cc)
{
    const ull onep = pack2(1.f, 1.f), negonep = pack2(-1.f, -1.f);
    const ull ccp = pack2(cc, cc);
#pragma unroll
    for (int jg = 0; jg < NREG; jg += 16) {
        ull A[8];
#pragma unroll
        for (int k = 0; k < 8; ++k) A[k] = 0ull;
#pragma unroll
        for (int wi = 0; wi < 3; ++wi) {
            unsigned w = (wi == 0) ? g0 : ((wi == 1) ? g1 : g2);
            const float* bp = shM + (wi * 16) * NREG + jg;
#pragma unroll 2
            for (int p = 0; p < 16; ++p) {
                unsigned be = (w >> (2 * p)) & 1u;
                unsigned bx = ((w >> (2 * p)) ^ (w >> (2 * p + 1))) & 1u;
                const ulonglong2* src = (const ulonglong2*)(bx ? (bp + PAIR_OFF) : bp);
                ull s2 = be ? onep : negonep;
#pragma unroll
                for (int t = 0; t < 4; ++t) {
                    ulonglong2 m = src[t];
                    A[2 * t]     = fma2(s2, m.x, A[2 * t]);
                    A[2 * t + 1] = fma2(s2, m.y, A[2 * t + 1]);
                }
                bp += NREG;
            }
        }
#pragma unroll
        for (int k = 0; k < 8; ++k) {
            int j = jg + 2 * k;
            int j0 = shOrd[j], j1 = shOrd[j + 1];
            ull xp2 = pack2(myscr[j0], myscr[j1]);           // original xp
            ull xm2 = fma2(vp[jg / 2 + k], negonep, xp2);    // x_mse = xp - r
            ull t = fma2(ccp, A[k], xm2);
            float ol, oh;
            unpack2(t, ol, oh);
            myscr[j0] = ol;
            myscr[j1] = oh;
        }
    }
}

// outlier pass 2 (codebook FFMA2, normal-form matrix); r left in vop, x_mse in xmo2
__device__ __forceinline__ float out_pass2(
    ull* vop, ull* xmo2, const float* shRo, unsigned code0, unsigned code1,
    float cO0, float cO1, float cO2, float cO3, ull nrmop)
{
    const ull negonep = pack2(-1.f, -1.f);
    ull A[16];
#pragma unroll
    for (int k = 0; k < 16; ++k) A[k] = 0ull;
#pragma unroll
    for (int wi = 0; wi < 2; ++wi) {
        unsigned w = (wi == 0) ? code0 : code1;
        const ulonglong2* mp = (const ulonglong2*)(shRo + (wi * 16) * NOUTC);
#pragma unroll 2
        for (int b = 0; b < 16; ++b) {
            unsigned idx = (w >> (2 * b)) & 3u;
            float lo = (idx & 1u) ? cO1 : cO0;
            float hi = (idx & 1u) ? cO3 : cO2;
            float yh = (idx & 2u) ? hi : lo;
            ull yh2 = pack2(yh, yh);
#pragma unroll
            for (int t = 0; t < 8; ++t) {
                ulonglong2 m = mp[t];
                A[2 * t]     = fma2(yh2, m.x, A[2 * t]);
                A[2 * t + 1] = fma2(yh2, m.y, A[2 * t + 1]);
            }
            mp += NOUTC / 4;
        }
    }
    ull rsqo2 = 0ull;
#pragma unroll
    for (int k = 0; k < 16; ++k) {
        ull xm2 = mul2(A[k], nrmop);
        xmo2[k] = xm2;
        ull r2 = fma2(xm2, negonep, vop[k]);
        vop[k] = r2;
        rsqo2 = fma2(r2, r2, rsqo2);
    }
    float sl, shh;
    unpack2(rsqo2, sl, shh);
    return fmaxf(sqrtf(sl + shh), 1e-10f);
}

// outlier pass 4 (pair FFMA2, bank-disjoint shSo)
__device__ __forceinline__ void out_pass4(
    const ull* xmo2, const float* shSo, const int* shOrd, float* myscr,
    unsigned gbo, float cc)
{
    const ull onep = pack2(1.f, 1.f);
    const ull negonep = pack2(-1.f, -1.f);
    const ull ccp = pack2(cc, cc);
    ull A[16];
#pragma unroll
    for (int k = 0; k < 16; ++k) A[k] = 0ull;
    const float* bp = shSo;
#pragma unroll 2
    for (int p = 0; p < 16; ++p) {
        unsigned be = (gbo >> (2 * p)) & 1u;
        unsigned bx = ((gbo >> (2 * p)) ^ (gbo >> (2 * p + 1))) & 1u;
        const ulonglong2* src = (const ulonglong2*)(bx ? (bp + PAIR_OFF_O) : bp);
        ull s2 = be ? onep : negonep;
#pragma unroll
        for (int t = 0; t < 8; ++t) {
            ulonglong2 m = src[t];
            A[2 * t]     = fma2(s2, m.x, A[2 * t]);
            A[2 * t + 1] = fma2(s2, m.y, A[2 * t + 1]);
        }
        bp += NOUTC;
    }
#pragma unroll
    for (int k = 0; k < 16; ++k) {
        ull t = fma2(ccp, A[k], xmo2[k]);
        float o0, o1;
        unpack2(t, o0, o1);
        myscr[shOrd[NREG + 2 * k]]     = o0;
        myscr[shOrd[NREG + 2 * k + 1]] = o1;
    }
}

// ---------------------------------------------------------------------------
// Stage C: fused roundtrip, TWO rows per thread; decision passes share one
//          matrix stream for both rows (1 pair/iter: minimal registers).
// ---------------------------------------------------------------------------
__global__ void __launch_bounds__(TPB, 1) k_main(
    const float* __restrict__ x,
    const float* __restrict__ rotR, const float* __restrict__ rotO,
    const float* __restrict__ cbR,  const float* __restrict__ cbO,
    const float* __restrict__ SR,   const float* __restrict__ SO,
    float* __restrict__ out)
{
    extern __shared__ float sh[];
    float* scr    = sh;                 // 256 rows x 129 floats
    float* shM    = sh + OFF_M;         // pair regions: P+ at 0, P- at PAIR_OFF
    float* shRo   = sh + OFF_RO;
    float* shSo   = sh + OFF_SO;
    int*   shOrd  = (int*)(sh + OFF_ORD);
    float* shCsR  = sh + OFF_CSR;

    const int bh  = blockIdx.y;
    const int tid = threadIdx.x;

    const size_t blockRowBase = (size_t)bh * SLEN + (size_t)blockIdx.x * RPB;
    const float4* xv   = (const float4*)(x   + blockRowBase * DIMC);
    float4*       outv = (float4*)      (out + blockRowBase * DIMC);

    // ---- coalesced fill of scratch (256-row x tile), matrices, order, colsum ----
#pragma unroll 4
    for (int i = tid; i < RPB * (DIMC / 4); i += TPB) {
        float4 t = xv[i];
        int row = i >> 5, c4 = (i & 31) * 4;
        float* d = scr + row * SCR_STRIDE + c4;
        d[0] = t.x; d[1] = t.y; d[2] = t.z; d[3] = t.w;
    }
#pragma unroll 4
    for (int k = 0; k < 36; ++k) {
        int idx = tid + k * TPB;                  // 0..4607
        int P = idx / NREG, j = idx - P * NREG;
        float a = __ldg(rotR + (2 * P) * NREG + j);
        float b = __ldg(rotR + (2 * P + 1) * NREG + j);
        shM[P * NREG + j]            = a + b;
        shM[PAIR_OFF + P * NREG + j] = a - b;
    }
    for (int i = tid; i < NOUTC * NOUTC; i += TPB) { shRo[i] = rotO[i]; shSo[i] = SO[i]; }
    if (tid < DIMC) shOrd[tid] = g_order[bh * DIMC + tid];
    if (tid < NREG) shCsR[tid] = g_colR[tid];
    __syncthreads();

    float* myA = scr + tid * SCR_STRIDE;
    float* myB = scr + (tid + TPB) * SCR_STRIDE;

    const float cR0 = __ldg(cbR), cR1 = __ldg(cbR + 1);
    const float midR = 0.5f * (cR0 + cR1);
    const float cO0 = __ldg(cbO), cO1 = __ldg(cbO + 1), cO2 = __ldg(cbO + 2), cO3 = __ldg(cbO + 3);
    const float mO0 = 0.5f * (cO0 + cO1), mO1 = 0.5f * (cO1 + cO2), mO2 = 0.5f * (cO2 + cO3);
    const float SCALE_R = 1.2533141373155003f / 96.0f;   // sqrt(pi/2)/96
    const float SCALE_O = 1.2533141373155003f / 32.0f;   // sqrt(pi/2)/32
    const float chalf = 0.5f * (cR1 - cR0);
    const ull cmidp   = pack2(midR, midR);
    const ull chalfp  = pack2(chalf, chalf);

    // ---------------- gather both rows (packed, from scratch) ----------------
    ull vpA[NREG / 2], vpB[NREG / 2];
    ull nsqA = 0ull, nsqB = 0ull;
#pragma unroll
    for (int p = 0; p < NREG / 2; ++p) {
        int o0 = shOrd[2 * p], o1 = shOrd[2 * p + 1];
        ull tA = pack2(myA[o0], myA[o1]);
        ull tB = pack2(myB[o0], myB[o1]);
        vpA[p] = tA;
        vpB[p] = tB;
        nsqA = fma2(tA, tA, nsqA);
        nsqB = fma2(tB, tB, nsqB);
    }
    float al, ah, bl, bhh;
    unpack2(nsqA, al, ah);
    unpack2(nsqB, bl, bhh);
    float nrmA = fmaxf(sqrtf(al + ah), 1e-8f);
    float nrmB = fmaxf(sqrtf(bl + bhh), 1e-8f);
    float hinvA = 0.5f / nrmA;
    float hinvB = 0.5f / nrmB;

    // -------- REG pass 1 (pair form, SHARED matrix stream; 1 pair/iter) --------
    unsigned sA0 = 0u, sA1 = 0u, sA2 = 0u;
    unsigned sB0 = 0u, sB1 = 0u, sB2 = 0u;
#pragma unroll 1
    for (int P = 0; P < 48; ++P) {
        const ulonglong2* rp = (const ulonglong2*)(shM + P * NREG);
        const ulonglong2* rm = (const ulonglong2*)(shM + PAIR_OFF + P * NREG);
        ull uA = 0ull, wA = 0ull, uB = 0ull, wB = 0ull;
#pragma unroll
        for (int q = 0; q < 24; ++q) {
            ull vA0 = vpA[2 * q], vA1 = vpA[2 * q + 1];
            ull vB0 = vpB[2 * q], vB1 = vpB[2 * q + 1];
            ulonglong2 mp = rp[q];
            uA = fma2(mp.x, vA0, uA); uA = fma2(mp.y, vA1, uA);
            uB = fma2(mp.x, vB0, uB); uB = fma2(mp.y, vB1, uB);
            ulonglong2 mm = rm[q];
            wA = fma2(mm.x, vA0, wA); wA = fma2(mm.y, vA1, wA);
            wB = fma2(mm.x, vB0, wB); wB = fma2(mm.y, vB1, wB);
        }
        float l0, h0, l1, h1;
        unpack2(uA, l0, h0); unpack2(wA, l1, h1);
        {
            float U = l0 + h0, W = l1 + h1;
            unsigned b =  (unsigned)((U + W) * hinvA > midR)
                       | ((unsigned)((U - W) * hinvA > midR) << 1);
            if      (P < 16) sA0 |= b << (2 * P);
            else if (P < 32) sA1 |= b << (2 * P - 32);
            else             sA2 |= b << (2 * P - 64);
        }
        unpack2(uB, l0, h0); unpack2(wB, l1, h1);
        {
            float U = l0 + h0, W = l1 + h1;
            unsigned b =  (unsigned)((U + W) * hinvB > midR)
                       | ((unsigned)((U - W) * hinvB > midR) << 1);
            if      (P < 16) sB0 |= b << (2 * P);
            else if (P < 32) sB1 |= b << (2 * P - 32);
            else             sB2 |= b << (2 * P - 64);
        }
    }

    // -------- REG pass 2 per row --------
    float rnA = rec_pass2(vpA, shM, shCsR, sA0, sA1, sA2, cmidp, chalfp, pack2(nrmA, nrmA));
    float rnB = rec_pass2(vpB, shM, shCsR, sB0, sB1, sB2, cmidp, chalfp, pack2(nrmB, nrmB));

    // load SR directly in split pair form from global
    __syncthreads();
#pragma unroll 4
    for (int k = 0; k < 36; ++k) {
        int idx = tid + k * TPB;
        int P = idx / NREG, j = idx - P * NREG;
        float a = __ldg(SR + (2 * P) * NREG + j);
        float b = __ldg(SR + (2 * P + 1) * NREG + j);
        shM[P * NREG + j]            = a + b;
        shM[PAIR_OFF + P * NREG + j] = a - b;
    }
    __syncthreads();

    // -------- REG pass 3 (pair form, SHARED stream; 1 pair/iter) --------
    unsigned gA0 = 0u, gA1 = 0u, gA2 = 0u;
    unsigned gB0 = 0u, gB1 = 0u, gB2 = 0u;
#pragma unroll 1
    for (int P = 0; P < 48; ++P) {
        const ulonglong2* rp = (const ulonglong2*)(shM + P * NREG);
        const ulonglong2* rm = (const ulonglong2*)(shM + PAIR_OFF + P * NREG);
        ull uA = 0ull, wA = 0ull, uB = 0ull, wB = 0ull;
#pragma unroll
        for (int q = 0; q < 24; ++q) {
            ull vA0 = vpA[2 * q], vA1 = vpA[2 * q + 1];
            ull vB0 = vpB[2 * q], vB1 = vpB[2 * q + 1];
            ulonglong2 mp = rp[q];
            uA = fma2(mp.x, vA0, uA); uA = fma2(mp.y, vA1, uA);
            uB = fma2(mp.x, vB0, uB); uB = fma2(mp.y, vB1, uB);
            ulonglong2 mm = rm[q];
            wA = fma2(mm.x, vA0, wA); wA = fma2(mm.y, vA1, wA);
            wB = fma2(mm.x, vB0, wB); wB = fma2(mm.y, vB1, wB);
        }
        float l0, h0, l1, h1;
        unpack2(uA, l0, h0); unpack2(wA, l1, h1);
        {
            float U = l0 + h0, W = l1 + h1;
            unsigned b =  (unsigned)((U + W) >= 0.f)
                       | ((unsigned)((U - W) >= 0.f) << 1);
            if      (P < 16) gA0 |= b << (2 * P);
            else if (P < 32) gA1 |= b << (2 * P - 32);
            else             gA2 |= b << (2 * P - 64);
        }
        unpack2(uB, l0, h0); unpack2(wB, l1, h1);
        {
            float U = l0 + h0, W = l1 + h1;
            unsigned b =  (unsigned)((U + W) >= 0.f)
                       | ((unsigned)((U - W) >= 0.f) << 1);
            if      (P < 16) gB0 |= b << (2 * P);
            else if (P < 32) gB1 |= b << (2 * P - 32);
            else             gB2 |= b << (2 * P - 64);
        }
    }

    // -------- REG pass 4 per row --------
    rec_pass4(vpA, shM, shOrd, myA, gA0, gA1, gA2, SCALE_R * rnA);
    rec_pass4(vpB, shM, shOrd, myB, gB0, gB1, gB2, SCALE_R * rnB);

    // =====================  OUTLIER subspace (32 dims, 2-bit)  =====================
    {
        ull voA[NOUTC / 2], voB[NOUTC / 2];
        ull nsqoA = 0ull, nsqoB = 0ull;
#pragma unroll
        for (int p = 0; p < NOUTC / 2; ++p) {
            int o0 = shOrd[NREG + 2 * p], o1 = shOrd[NREG + 2 * p + 1];
            ull tA = pack2(myA[o0], myA[o1]);
            ull tB = pack2(myB[o0], myB[o1]);
            voA[p] = tA; voB[p] = tB;
            nsqoA = fma2(tA, tA, nsqoA);
            nsqoB = fma2(tB, tB, nsqoB);
        }
        float l, h;
        unpack2(nsqoA, l, h);
        float nrmoA = fmaxf(sqrtf(l + h), 1e-8f);
        unpack2(nsqoB, l, h);
        float nrmoB = fmaxf(sqrtf(l + h), 1e-8f);
        float invoA = 1.0f / nrmoA, invoB = 1.0f / nrmoB;

        // pass 1 (SHARED stream, 1 matrix row per iter): 2-bit codes for both rows
        unsigned cA0 = 0u, cA1 = 0u, cB0 = 0u, cB1 = 0u;
#pragma unroll 1
        for (int i = 0; i < NOUTC; ++i) {
            const ulonglong2* r0 = (const ulonglong2*)(shRo + i * NOUTC);
            ull aA = 0ull, aB = 0ull;
#pragma unroll
            for (int q = 0; q < 8; ++q) {
                ull vA0 = voA[2 * q], vA1 = voA[2 * q + 1];
                ull vB0 = voB[2 * q], vB1 = voB[2 * q + 1];
                ulonglong2 m = r0[q];
                aA = fma2(m.x, vA0, aA); aA = fma2(m.y, vA1, aA);
                aB = fma2(m.x, vB0, aB); aB = fma2(m.y, vB1, aB);
            }
            float l0, h0;
            unpack2(aA, l0, h0);
            {
                float y = (l0 + h0) * invoA;
                unsigned c = (unsigned)(y > mO0) + (unsigned)(y > mO1) + (unsigned)(y > mO2);
                if (i < 16) cA0 |= c << (2 * i);
                else        cA1 |= c << (2 * i - 32);
            }
            unpack2(aB, l0, h0);
            {
                float y = (l0 + h0) * invoB;
                unsigned c = (unsigned)(y > mO0) + (unsigned)(y > mO1) + (unsigned)(y > mO2);
                if (i < 16) cB0 |= c << (2 * i);
                else        cB1 |= c << (2 * i - 32);
            }
        }

        // pass 2 per row
        ull xmoA[NOUTC / 2], xmoB[NOUTC / 2];
        float rnoA = out_pass2(voA, xmoA, shRo, cA0, cA1, cO0, cO1, cO2, cO3, pack2(nrmoA, nrmoA));
        float rnoB = out_pass2(voB, xmoB, shRo, cB0, cB1, cO0, cO1, cO2, cO3, pack2(nrmoB, nrmoB));

        // pass 3 (SHARED stream, 1 matrix row per iter): signs for both rows
        unsigned gboA = 0u, gboB = 0u;
#pragma unroll 1
        for (int i = 0; i < NOUTC; ++i) {
            const ulonglong2* r0 = (const ulonglong2*)(shSo + i * NOUTC);
            ull aA = 0ull, aB = 0ull;
#pragma unroll
            for (int q = 0; q < 8; ++q) {
                ull vA0 = voA[2 * q], vA1 = voA[2 * q + 1];
                ull vB0 = voB[2 * q], vB1 = voB[2 * q + 1];
                ulonglong2 m = r0[q];
                aA = fma2(m.x, vA0, aA); aA = fma2(m.y, vA1, aA);
                aB = fma2(m.x, vB0, aB); aB = fma2(m.y, vB1, aB);
            }
            float l0, h0;
            unpack2(aA, l0, h0);
            gboA |= (unsigned)((l0 + h0) >= 0.f) << i;
            unpack2(aB, l0, h0);
            gboB |= (unsigned)((l0 + h0) >= 0.f) << i;
        }

        // ---- register-staged transform shSo -> split pair form ----
        {
            float s4[4], d4[4];
            __syncthreads();
#pragma unroll
            for (int k = 0; k < 4; ++k) {
                int idx = tid + k * TPB;              // 0..511
                int P = idx / NOUTC, j = idx - P * NOUTC;
                float a = shSo[(2 * P) * NOUTC + j];
                float b = shSo[(2 * P + 1) * NOUTC + j];
                s4[k] = a + b;
                d4[k] = a - b;
            }
            __syncthreads();
#pragma unroll
            for (int k = 0; k < 4; ++k) {
                int idx = tid + k * TPB;
                int P = idx / NOUTC, j = idx - P * NOUTC;
                shSo[P * NOUTC + j]              = s4[k];
                shSo[PAIR_OFF_O + P * NOUTC + j] = d4[k];
            }
            __syncthreads();
        }

        // pass 4 per row
        out_pass4(xmoA, shSo, shOrd, myA, gboA, SCALE_O * rnoA);
        out_pass4(xmoB, shSo, shOrd, myB, gboB, SCALE_O * rnoB);
    }

    // ---- coalesced copy-out of finished rows ----
    __syncthreads();
#pragma unroll 4
    for (int i = tid; i < RPB * (DIMC / 4); i += TPB) {
        int row = i >> 5, c4 = (i & 31) * 4;
        const float* s = scr + row * SCR_STRIDE + c4;
        outv[i] = make_float4(s[0], s[1], s[2], s[3]);
    }
}

// ---------------------------------------------------------------------------
extern "C" void kernel_launch(void* const* d_in, const int* in_sizes, int n_in,
                              void* d_out, int out_size)
{
    const float* x    = (const float*)d_in[0];
    const float* rotR = (const float*)d_in[1];
    const float* rotO = (const float*)d_in[2];
    const float* cbR  = (const float*)d_in[3];
    const float* cbO  = (const float*)d_in[4];
    const float* SR   = (const float*)d_in[5];
    const float* SO   = (const float*)d_in[6];
    float* out = (float*)d_out;

    static int smem_set = 0;
    if (!smem_set) {
        cudaFuncSetAttribute(k_main, cudaFuncAttributeMaxDynamicSharedMemorySize, SMEM_BYTES);
        smem_set = 1;
    }

    dim3 gA(NCHUNK, NBH);
    k_chnorm<<<gA, DIMC>>>(x);
    k_order<<<NBH, DIMC>>>();
    k_colsum<<<1, DIMC>>>(rotR);
    dim3 gM(SLEN / RPB, NBH);
    k_main<<<gM, TPB, SMEM_BYTES>>>(x, rotR, rotO, cbR, cbO, SR, SO, out);
}

// round 15
// speedup vs baseline: 1.4189x; 1.4189x over previous
#include <cuda_runtime.h>
#include <math.h>

// Shapes (fixed): x = (4,8,8192,128) fp32
#define NBH     32
#define SLEN    8192
#define DIMC    128
#define NREG    96
#define NOUTC   32
#define TPB     128
#define NCHUNK  32
#define CHUNK_S 256   // SLEN / NCHUNK

#define PAIR_OFF   4624                       // floats; 18496 B == 64 mod 128 -> disjoint banks
#define PAIR_OFF_O 528                        // floats; 2112 B == 64 mod 128

#define SCR_STRIDE 129                        // conflict-free scattered access
#define SCR_FLOATS (TPB * SCR_STRIDE)         // 16512 (byte off 0, 128B-aligned)
#define OFF_M      SCR_FLOATS                 // shM: pair regions (2 x 48 x 96)
#define OFF_RO     (OFF_M + 9248)             // shRo: 32*32
#define OFF_SO     (OFF_RO + 1024)            // shSo: 32*32 + pair pad; 128B-aligned
#define OFF_ORD    (OFF_SO + 1040)            // 128 ints
#define OFF_CSR    (OFF_ORD + DIMC)           // colsum(rotR): 96
#define SMEM_FLOATS (OFF_CSR + NREG)
#define SMEM_BYTES  (SMEM_FLOATS * 4)

typedef unsigned long long ull;

// static device scratch (no runtime allocation)
__device__ float g_partial[NBH * NCHUNK * DIMC];
__device__ int   g_order[NBH * DIMC];
__device__ float g_colR[NREG];

// ---------------------------------------------------------------------------
// packed f32x2 helpers (FFMA2 path on sm_103a)
// ---------------------------------------------------------------------------
__device__ __forceinline__ ull pack2(float lo, float hi)
{
    ull r;
    asm("mov.b64 %0, {%1, %2};" : "=l"(r) : "f"(lo), "f"(hi));
    return r;
}
__device__ __forceinline__ void unpack2(ull p, float& lo, float& hi)
{
    asm("mov.b64 {%0, %1}, %2;" : "=f"(lo), "=f"(hi) : "l"(p));
}
__device__ __forceinline__ ull fma2(ull a, ull b, ull c)
{
    ull d;
    asm("fma.rn.f32x2 %0, %1, %2, %3;" : "=l"(d) : "l"(a), "l"(b), "l"(c));
    return d;
}
__device__ __forceinline__ ull mul2(ull a, ull b)
{
    ull d;
    asm("mul.rn.f32x2 %0, %1, %2;" : "=l"(d) : "l"(a), "l"(b));
    return d;
}

// ---------------------------------------------------------------------------
// Stage A: partial channel sum-of-squares (coalesced, deep MLP)
// ---------------------------------------------------------------------------
__global__ void __launch_bounds__(DIMC) k_chnorm(const float* __restrict__ x)
{
    int bh = blockIdx.y, ck = blockIdx.x, c = threadIdx.x;
    const float* p = x + ((size_t)bh * SLEN + (size_t)ck * CHUNK_S) * DIMC + c;
    float acc = 0.f;
#pragma unroll 16
    for (int s = 0; s < CHUNK_S; ++s) {
        float t = p[(size_t)s * DIMC];
        acc = fmaf(t, t, acc);
    }
    g_partial[(bh * NCHUNK + ck) * DIMC + c] = acc;
}

// ---------------------------------------------------------------------------
// Stage B (merged): blocks 0..NBH-1: reduce + top-32 + stable order;
//                   block NBH: column sums of rotR.
// ---------------------------------------------------------------------------
__global__ void __launch_bounds__(DIMC) k_order(const float* __restrict__ rotR)
{
    if (blockIdx.x == NBH) {
        int j = threadIdx.x;
        if (j < NREG) {
            float a = 0.f;
            for (int i = 0; i < NREG; ++i) a += rotR[i * NREG + j];
            g_colR[j] = a;
        }
        return;
    }
    __shared__ float nsq[DIMC];
    __shared__ int   flag[DIMC];
    int bh = blockIdx.x, c = threadIdx.x;
    float a = 0.f;
    for (int k = 0; k < NCHUNK; ++k) a += g_partial[(bh * NCHUNK + k) * DIMC + c];
    nsq[c] = a;
    __syncthreads();
    int rank = 0;
    for (int d = 0; d < DIMC; ++d) {
        float nd = nsq[d];
        rank += (nd > a) || (nd == a && d < c);   // top_k ties: lower index wins
    }
    int isout = (rank < NOUTC) ? 1 : 0;
    flag[c] = isout;
    __syncthreads();
    int pos = 0;
    for (int d = 0; d < c; ++d) pos += (flag[d] == isout);
    g_order[bh * DIMC + (isout ? (NREG + pos) : pos)] = c;
}

// ---------------------------------------------------------------------------
// Stage C: fused roundtrip; all 96-dim passes run from bank-disjoint pair
//          form (P+ = Me+Mo, P- = Me-Mo) loaded directly from global.
//          (R12 champion structure, unroll depths tuned for no spills.)
// ---------------------------------------------------------------------------
__global__ void __launch_bounds__(TPB, 2) k_main(
    const float* __restrict__ x,
    const float* __restrict__ rotR, const float* __restrict__ rotO,
    const float* __restrict__ cbR,  const float* __restrict__ cbO,
    const float* __restrict__ SR,   const float* __restrict__ SO,
    float* __restrict__ out)
{
    extern __shared__ float sh[];
    float* scr    = sh;                 // 128 rows x 129 floats
    float* shM    = sh + OFF_M;         // pair regions: P+ at 0, P- at PAIR_OFF
    float* shRo   = sh + OFF_RO;
    float* shSo   = sh + OFF_SO;
    int*   shOrd  = (int*)(sh + OFF_ORD);
    float* shCsR  = sh + OFF_CSR;

    const int bh  = blockIdx.y;
    const int tid = threadIdx.x;

    const size_t blockRowBase = (size_t)bh * SLEN + (size_t)blockIdx.x * TPB;
    const float4* xv   = (const float4*)(x   + blockRowBase * DIMC);
    float4*       outv = (float4*)      (out + blockRowBase * DIMC);

    // ---- coalesced fill of scratch (x tile), matrices, order, colsum ----
#pragma unroll 4
    for (int i = tid; i < TPB * (DIMC / 4); i += TPB) {
        float4 t = xv[i];
        int row = i >> 5, c4 = (i & 31) * 4;
        float* d = scr + row * SCR_STRIDE + c4;
        d[0] = t.x; d[1] = t.y; d[2] = t.z; d[3] = t.w;
    }
    // rotR directly in split pair form from global (bounded unroll: low reg pressure)
#pragma unroll 4
    for (int k = 0; k < 36; ++k) {
        int idx = tid + k * TPB;                  // 0..4607
        int P = idx / NREG, j = idx - P * NREG;
        float a = __ldg(rotR + (2 * P) * NREG + j);
        float b = __ldg(rotR + (2 * P + 1) * NREG + j);
        shM[P * NREG + j]            = a + b;
        shM[PAIR_OFF + P * NREG + j] = a - b;
    }
    for (int i = tid; i < NOUTC * NOUTC; i += TPB) { shRo[i] = rotO[i]; shSo[i] = SO[i]; }
    if (tid < DIMC) shOrd[tid] = g_order[bh * DIMC + tid];
    if (tid < NREG) shCsR[tid] = g_colR[tid];
    __syncthreads();

    float* myscr = scr + tid * SCR_STRIDE;   // this thread's row (conflict-free scattered)

    const float cR0 = __ldg(cbR), cR1 = __ldg(cbR + 1);
    const float midR = 0.5f * (cR0 + cR1);
    const float cO0 = __ldg(cbO), cO1 = __ldg(cbO + 1), cO2 = __ldg(cbO + 2), cO3 = __ldg(cbO + 3);
    const float mO0 = 0.5f * (cO0 + cO1), mO1 = 0.5f * (cO1 + cO2), mO2 = 0.5f * (cO2 + cO3);
    const float SCALE_R = 1.2533141373155003f / 96.0f;   // sqrt(pi/2)/96
    const float SCALE_O = 1.2533141373155003f / 32.0f;   // sqrt(pi/2)/32

    const ull onep    = pack2(1.f, 1.f);
    const ull negonep = pack2(-1.f, -1.f);
    const float chalf = 0.5f * (cR1 - cR0);
    const ull cmidp   = pack2(midR, midR);
    const ull chalfp  = pack2(chalf, chalf);

    // ---------------- gather regular subspace (packed, from scratch) ----------------
    ull vp[NREG / 2];
    ull nsq2 = 0ull;
#pragma unroll
    for (int p = 0; p < NREG / 2; ++p) {
        float a = myscr[shOrd[2 * p]];
        float b = myscr[shOrd[2 * p + 1]];
        ull t = pack2(a, b);
        vp[p] = t;
        nsq2 = fma2(t, t, nsq2);
    }
    float nl, nh;
    unpack2(nsq2, nl, nh);
    float nrm = fmaxf(sqrtf(nl + nh), 1e-8f);
    float inv = 1.0f / nrm;
    const float hinv = 0.5f * inv;
    const ull nrmp = pack2(nrm, nrm);

    // -------- REG pass 1 (pair form): u = P+.v, w = P-.v ;
    //          y_e = (u+w)*hinv, y_o = (u-w)*hinv -> 1-bit codes --------
    unsigned sb0 = 0u, sb1 = 0u, sb2 = 0u;
#pragma unroll 1
    for (int ig = 0; ig < 24; ++ig) {
        const ulonglong2* rp0 = (const ulonglong2*)(shM + (2 * ig) * NREG);
        const ulonglong2* rm0 = (const ulonglong2*)(shM + PAIR_OFF + (2 * ig) * NREG);
        const ulonglong2* rp1 = (const ulonglong2*)(shM + (2 * ig + 1) * NREG);
        const ulonglong2* rm1 = (const ulonglong2*)(shM + PAIR_OFF + (2 * ig + 1) * NREG);
        ull a0 = 0ull, a1 = 0ull, a2 = 0ull, a3 = 0ull;
#pragma unroll
        for (int q = 0; q < 24; ++q) {
            ull v0 = vp[2 * q], v1 = vp[2 * q + 1];
            ulonglong2 m0 = rp0[q]; a0 = fma2(m0.x, v0, a0); a0 = fma2(m0.y, v1, a0);
            ulonglong2 m1 = rm0[q]; a1 = fma2(m1.x, v0, a1); a1 = fma2(m1.y, v1, a1);
            ulonglong2 m2 = rp1[q]; a2 = fma2(m2.x, v0, a2); a2 = fma2(m2.y, v1, a2);
            ulonglong2 m3 = rm1[q]; a3 = fma2(m3.x, v0, a3); a3 = fma2(m3.y, v1, a3);
        }
        float l0, h0, l1, h1, l2, h2, l3, h3;
        unpack2(a0, l0, h0); unpack2(a1, l1, h1);
        unpack2(a2, l2, h2); unpack2(a3, l3, h3);
        float U0 = l0 + h0, W0 = l1 + h1;
        float U1 = l2 + h2, W1 = l3 + h3;
        unsigned b =  (unsigned)((U0 + W0) * hinv > midR)
                   | ((unsigned)((U0 - W0) * hinv > midR) << 1)
                   | ((unsigned)((U1 + W1) * hinv > midR) << 2)
                   | ((unsigned)((U1 - W1) * hinv > midR) << 3);
        if      (ig < 8)  sb0 |= b << (ig * 4);
        else if (ig < 16) sb1 |= b << ((ig - 8) * 4);
        else              sb2 |= b << ((ig - 16) * 4);
    }

    // ------- REG pass 2 (pair FFMA2, bank-disjoint): T = sum_i sigma_i rot_i ;
    //         x_mse = nrm*(cmid*colsum + chalf*T) ; r = xp - x_mse (no stash) -------
    ull rsq2 = 0ull;
#pragma unroll
    for (int jg = 0; jg < NREG; jg += 32) {
        ull A[16];
#pragma unroll
        for (int k = 0; k < 16; ++k) A[k] = 0ull;
#pragma unroll
        for (int wi = 0; wi < 3; ++wi) {
            unsigned w = (wi == 0) ? sb0 : ((wi == 1) ? sb1 : sb2);
            const float* bp = shM + (wi * 16) * NREG + jg;   // pair base (P+)
#pragma unroll 2
            for (int p = 0; p < 16; ++p) {
                unsigned be = (w >> (2 * p)) & 1u;
                unsigned bx = ((w >> (2 * p)) ^ (w >> (2 * p + 1))) & 1u;
                const ulonglong2* src = (const ulonglong2*)(bx ? (bp + PAIR_OFF) : bp);
                ull s2 = be ? onep : negonep;
#pragma unroll
                for (int t = 0; t < 8; ++t) {
                    ulonglong2 m = src[t];
                    A[2 * t]     = fma2(s2, m.x, A[2 * t]);
                    A[2 * t + 1] = fma2(s2, m.y, A[2 * t + 1]);
                }
                bp += NREG;
            }
        }
#pragma unroll
        for (int k = 0; k < 16; ++k) {
            ull cs2 = *(const ull*)(shCsR + jg + 2 * k);
            ull t = mul2(cmidp, cs2);
            t = fma2(chalfp, A[k], t);
            ull xm2 = mul2(t, nrmp);
            ull r2 = fma2(xm2, negonep, vp[jg / 2 + k]);
            vp[jg / 2 + k] = r2;
            rsq2 = fma2(r2, r2, rsq2);
        }
    }
    float rl, rh;
    unpack2(rsq2, rl, rh);
    float rn = fmaxf(sqrtf(rl + rh), 1e-10f);

    // load SR directly in split pair form from global (bounded unroll)
    __syncthreads();
#pragma unroll 4
    for (int k = 0; k < 36; ++k) {
        int idx = tid + k * TPB;
        int P = idx / NREG, j = idx - P * NREG;
        float a = __ldg(SR + (2 * P) * NREG + j);
        float b = __ldg(SR + (2 * P + 1) * NREG + j);
        shM[P * NREG + j]            = a + b;
        shM[PAIR_OFF + P * NREG + j] = a - b;
    }
    __syncthreads();

    // -------- REG pass 3 (pair form): u = P+.r, w = P-.r ;
    //          sign_e = (u+w)>=0, sign_o = (u-w)>=0 --------
    unsigned gb0 = 0u, gb1 = 0u, gb2 = 0u;
#pragma unroll 1
    for (int ig = 0; ig < 24; ++ig) {
        const ulonglong2* rp0 = (const ulonglong2*)(shM + (2 * ig) * NREG);
        const ulonglong2* rm0 = (const ulonglong2*)(shM + PAIR_OFF + (2 * ig) * NREG);
        const ulonglong2* rp1 = (const ulonglong2*)(shM + (2 * ig + 1) * NREG);
        const ulonglong2* rm1 = (const ulonglong2*)(shM + PAIR_OFF + (2 * ig + 1) * NREG);
        ull a0 = 0ull, a1 = 0ull, a2 = 0ull, a3 = 0ull;
#pragma unroll
        for (int q = 0; q < 24; ++q) {
            ull v0 = vp[2 * q], v1 = vp[2 * q + 1];
            ulonglong2 m0 = rp0[q]; a0 = fma2(m0.x, v0, a0); a0 = fma2(m0.y, v1, a0);
            ulonglong2 m1 = rm0[q]; a1 = fma2(m1.x, v0, a1); a1 = fma2(m1.y, v1, a1);
            ulonglong2 m2 = rp1[q]; a2 = fma2(m2.x, v0, a2); a2 = fma2(m2.y, v1, a2);
            ulonglong2 m3 = rm1[q]; a3 = fma2(m3.x, v0, a3); a3 = fma2(m3.y, v1, a3);
        }
        float l0, h0, l1, h1, l2, h2, l3, h3;
        unpack2(a0, l0, h0); unpack2(a1, l1, h1);
        unpack2(a2, l2, h2); unpack2(a3, l3, h3);
        float U0 = l0 + h0, W0 = l1 + h1;
        float U1 = l2 + h2, W1 = l3 + h3;
        unsigned b =  (unsigned)((U0 + W0) >= 0.f)
                   | ((unsigned)((U0 - W0) >= 0.f) << 1)
                   | ((unsigned)((U1 + W1) >= 0.f) << 2)
                   | ((unsigned)((U1 - W1) >= 0.f) << 3);
        if      (ig < 8)  gb0 |= b << (ig * 4);
        else if (ig < 16) gb1 |= b << ((ig - 8) * 4);
        else              gb2 |= b << ((ig - 16) * 4);
    }

    // ------- REG pass 4 (pair FFMA2, bank-disjoint): P = sum_i s_i S_i ;
    //         out = (xp - r) + cc*P  (xp read from untouched scratch) -------
    {
        float cc = SCALE_R * rn;
        const ull ccp = pack2(cc, cc);
#pragma unroll
        for (int jg = 0; jg < NREG; jg += 32) {
            ull A[16];
#pragma unroll
            for (int k = 0; k < 16; ++k) A[k] = 0ull;
#pragma unroll
            for (int wi = 0; wi < 3; ++wi) {
                unsigned w = (wi == 0) ? gb0 : ((wi == 1) ? gb1 : gb2);
                const float* bp = shM + (wi * 16) * NREG + jg;
#pragma unroll 2
                for (int p = 0; p < 16; ++p) {
                    unsigned be = (w >> (2 * p)) & 1u;
                    unsigned bx = ((w >> (2 * p)) ^ (w >> (2 * p + 1))) & 1u;
                    const ulonglong2* src = (const ulonglong2*)(bx ? (bp + PAIR_OFF) : bp);
                    ull s2 = be ? onep : negonep;
#pragma unroll
                    for (int t = 0; t < 8; ++t) {
                        ulonglong2 m = src[t];
                        A[2 * t]     = fma2(s2, m.x, A[2 * t]);
                        A[2 * t + 1] = fma2(s2, m.y, A[2 * t + 1]);
                    }
                    bp += NREG;
                }
            }
#pragma unroll
            for (int k = 0; k < 16; ++k) {
                int j = jg + 2 * k;
                int j0 = shOrd[j], j1 = shOrd[j + 1];
                ull xp2 = pack2(myscr[j0], myscr[j1]);              // original xp
                ull xm2 = fma2(vp[jg / 2 + k], negonep, xp2);       // x_mse = xp - r
                ull t = fma2(ccp, A[k], xm2);
                float ol, oh;
                unpack2(t, ol, oh);
                myscr[j0] = ol;
                myscr[j1] = oh;
            }
        }
    }

    // =====================  OUTLIER subspace (32 dims, 2-bit)  =====================
    ull vop[NOUTC / 2];
    ull nsqo2 = 0ull;
#pragma unroll
    for (int p = 0; p < NOUTC / 2; ++p) {
        float a = myscr[shOrd[NREG + 2 * p]];   // untouched slots
        float b = myscr[shOrd[NREG + 2 * p + 1]];
        ull t = pack2(a, b);
        vop[p] = t;
        nsqo2 = fma2(t, t, nsqo2);
    }
    {
        float ol, oh;
        unpack2(nsqo2, ol, oh);
        float nrmo = fmaxf(sqrtf(ol + oh), 1e-8f);
        float invo = 1.0f / nrmo;
        const ull nrmop = pack2(nrmo, nrmo);

        // pass 1: 2-bit codes
        unsigned code0 = 0u, code1 = 0u;
#pragma unroll 1
        for (int ig = 0; ig < 8; ++ig) {
            const ulonglong2* r0 = (const ulonglong2*)(shRo + (4 * ig + 0) * NOUTC);
            const ulonglong2* r1 = (const ulonglong2*)(shRo + (4 * ig + 1) * NOUTC);
            const ulonglong2* r2 = (const ulonglong2*)(shRo + (4 * ig + 2) * NOUTC);
            const ulonglong2* r3 = (const ulonglong2*)(shRo + (4 * ig + 3) * NOUTC);
            ull a0 = 0ull, a1 = 0ull, a2 = 0ull, a3 = 0ull;
#pragma unroll
            for (int q = 0; q < 8; ++q) {
                ull v0 = vop[2 * q], v1 = vop[2 * q + 1];
                ulonglong2 m0 = r0[q]; a0 = fma2(m0.x, v0, a0); a0 = fma2(m0.y, v1, a0);
                ulonglong2 m1 = r1[q]; a1 = fma2(m1.x, v0, a1); a1 = fma2(m1.y, v1, a1);
                ulonglong2 m2 = r2[q]; a2 = fma2(m2.x, v0, a2); a2 = fma2(m2.y, v1, a2);
                ulonglong2 m3 = r3[q]; a3 = fma2(m3.x, v0, a3); a3 = fma2(m3.y, v1, a3);
            }
            float l0, h0, l1, h1, l2, h2, l3, h3;
            unpack2(a0, l0, h0); unpack2(a1, l1, h1);
            unpack2(a2, l2, h2); unpack2(a3, l3, h3);
            float y0 = (l0 + h0) * invo, y1 = (l1 + h1) * invo;
            float y2 = (l2 + h2) * invo, y3 = (l3 + h3) * invo;
            unsigned i0 = (unsigned)(y0 > mO0) + (unsigned)(y0 > mO1) + (unsigned)(y0 > mO2);
            unsigned i1 = (unsigned)(y1 > mO0) + (unsigned)(y1 > mO1) + (unsigned)(y1 > mO2);
            unsigned i2 = (unsigned)(y2 > mO0) + (unsigned)(y2 > mO1) + (unsigned)(y2 > mO2);
            unsigned i3 = (unsigned)(y3 > mO0) + (unsigned)(y3 > mO1) + (unsigned)(y3 > mO2);
            unsigned b8 = i0 | (i1 << 2) | (i2 << 4) | (i3 << 6);
            if (ig < 4) code0 |= b8 << (ig * 8);
            else        code1 |= b8 << ((ig - 4) * 8);
        }

        // pass 2: x_mse (regs), r in vop  (FFMA2 form: 4-level codebook)
        ull xmo2[NOUTC / 2];
        ull rsqo2 = 0ull;
        {
            ull A[16];
#pragma unroll
            for (int k = 0; k < 16; ++k) A[k] = 0ull;
#pragma unroll
            for (int wi = 0; wi < 2; ++wi) {
                unsigned w = (wi == 0) ? code0 : code1;
                const ulonglong2* mp = (const ulonglong2*)(shRo + (wi * 16) * NOUTC);
#pragma unroll 2
                for (int b = 0; b < 16; ++b) {
                    unsigned idx = (w >> (2 * b)) & 3u;
                    float lo = (idx & 1u) ? cO1 : cO0;
                    float hi = (idx & 1u) ? cO3 : cO2;
                    float yh = (idx & 2u) ? hi : lo;
                    ull yh2 = pack2(yh, yh);
#pragma unroll
                    for (int t = 0; t < 8; ++t) {
                        ulonglong2 m = mp[t];
                        A[2 * t]     = fma2(yh2, m.x, A[2 * t]);
                        A[2 * t + 1] = fma2(yh2, m.y, A[2 * t + 1]);
                    }
                    mp += NOUTC / 4;
                }
            }
#pragma unroll
            for (int k = 0; k < 16; ++k) {
                ull xm2 = mul2(A[k], nrmop);
                xmo2[k] = xm2;
                ull r2 = fma2(xm2, negonep, vop[k]);
                vop[k] = r2;
                rsqo2 = fma2(r2, r2, rsqo2);
            }
        }
        float sl, shh;
        unpack2(rsqo2, sl, shh);
        float rno = fmaxf(sqrtf(sl + shh), 1e-10f);

        // pass 3: sign(S_out @ r)   (shSo normal form)
        unsigned gbo = 0u;
#pragma unroll 1
        for (int ig = 0; ig < 8; ++ig) {
            const ulonglong2* r0 = (const ulonglong2*)(shSo + (4 * ig + 0) * NOUTC);
            const ulonglong2* r1 = (const ulonglong2*)(shSo + (4 * ig + 1) * NOUTC);
            const ulonglong2* r2 = (const ulonglong2*)(shSo + (4 * ig + 2) * NOUTC);
            const ulonglong2* r3 = (const ulonglong2*)(shSo + (4 * ig + 3) * NOUTC);
            ull a0 = 0ull, a1 = 0ull, a2 = 0ull, a3 = 0ull;
#pragma unroll
            for (int q = 0; q < 8; ++q) {
                ull v0 = vop[2 * q], v1 = vop[2 * q + 1];
                ulonglong2 m0 = r0[q]; a0 = fma2(m0.x, v0, a0); a0 = fma2(m0.y, v1, a0);
                ulonglong2 m1 = r1[q]; a1 = fma2(m1.x, v0, a1); a1 = fma2(m1.y, v1, a1);
                ulonglong2 m2 = r2[q]; a2 = fma2(m2.x, v0, a2); a2 = fma2(m2.y, v1, a2);
                ulonglong2 m3 = r3[q]; a3 = fma2(m3.x, v0, a3); a3 = fma2(m3.y, v1, a3);
            }
            float l0, h0, l1, h1, l2, h2, l3, h3;
            unpack2(a0, l0, h0); unpack2(a1, l1, h1);
            unpack2(a2, l2, h2); unpack2(a3, l3, h3);
            unsigned b =  (unsigned)((l0 + h0) >= 0.f)
                       | ((unsigned)((l1 + h1) >= 0.f) << 1)
                       | ((unsigned)((l2 + h2) >= 0.f) << 2)
                       | ((unsigned)((l3 + h3) >= 0.f) << 3);
            gbo |= b << (ig * 4);
        }

        // ---- register-staged transform shSo -> split pair form ----
        {
            float s4[4], d4[4];
            __syncthreads();
#pragma unroll
            for (int k = 0; k < 4; ++k) {
                int idx = tid + k * TPB;              // 0..511
                int P = idx / NOUTC, j = idx - P * NOUTC;
                float a = shSo[(2 * P) * NOUTC + j];
                float b = shSo[(2 * P + 1) * NOUTC + j];
                s4[k] = a + b;
                d4[k] = a - b;
            }
            __syncthreads();
#pragma unroll
            for (int k = 0; k < 4; ++k) {
                int idx = tid + k * TPB;
                int P = idx / NOUTC, j = idx - P * NOUTC;
                shSo[P * NOUTC + j]              = s4[k];
                shSo[PAIR_OFF_O + P * NOUTC + j] = d4[k];
            }
            __syncthreads();
        }

        // pass 4 (pair FFMA2, bank-disjoint): P = sum_i s_i SO_i ; out = x_mse + cc*P
        {
            float cc = SCALE_O * rno;
            const ull ccp = pack2(cc, cc);
            ull A[16];
#pragma unroll
            for (int k = 0; k < 16; ++k) A[k] = 0ull;
            const float* bp = shSo;
#pragma unroll 2
            for (int p = 0; p < 16; ++p) {
                unsigned be = (gbo >> (2 * p)) & 1u;
                unsigned bx = ((gbo >> (2 * p)) ^ (gbo >> (2 * p + 1))) & 1u;
                const ulonglong2* src = (const ulonglong2*)(bx ? (bp + PAIR_OFF_O) : bp);
                ull s2 = be ? onep : negonep;
#pragma unroll
                for (int t = 0; t < 8; ++t) {
                    ulonglong2 m = src[t];
                    A[2 * t]     = fma2(s2, m.x, A[2 * t]);
                    A[2 * t + 1] = fma2(s2, m.y, A[2 * t + 1]);
                }
                bp += NOUTC;
            }
#pragma unroll
            for (int k = 0; k < 16; ++k) {
                ull t = fma2(ccp, A[k], xmo2[k]);
                float o0, o1;
                unpack2(t, o0, o1);
                myscr[shOrd[NREG + 2 * k]]     = o0;
                myscr[shOrd[NREG + 2 * k + 1]] = o1;
            }
        }
    }

    // ---- coalesced copy-out of finished rows ----
    __syncthreads();
#pragma unroll 4
    for (int i = tid; i < TPB * (DIMC / 4); i += TPB) {
        int row = i >> 5, c4 = (i & 31) * 4;
        const float* s = scr + row * SCR_STRIDE + c4;
        outv[i] = make_float4(s[0], s[1], s[2], s[3]);
    }
}

// ---------------------------------------------------------------------------
extern "C" void kernel_launch(void* const* d_in, const int* in_sizes, int n_in,
                              void* d_out, int out_size)
{
    const float* x    = (const float*)d_in[0];
    const float* rotR = (const float*)d_in[1];
    const float* rotO = (const float*)d_in[2];
    const float* cbR  = (const float*)d_in[3];
    const float* cbO  = (const float*)d_in[4];
    const float* SR   = (const float*)d_in[5];
    const float* SO   = (const float*)d_in[6];
    float* out = (float*)d_out;

    static int smem_set = 0;
    if (!smem_set) {
        cudaFuncSetAttribute(k_main, cudaFuncAttributeMaxDynamicSharedMemorySize, SMEM_BYTES);
        smem_set = 1;
    }

    dim3 gA(NCHUNK, NBH);
    k_chnorm<<<gA, DIMC>>>(x);
    k_order<<<NBH + 1, DIMC>>>(rotR);
    dim3 gM(SLEN / TPB, NBH);
    k_main<<<gM, TPB, SMEM_BYTES>>>(x, rotR, rotO, cbR, cbO, SR, SO, out);
}